// round 4
// baseline (speedup 1.0000x reference)
#include <cuda_runtime.h>

// Problem shape (fixed by reference setup_inputs): [B=64, S=2048, D=512] fp32
constexpr int B = 64;
constexpr int S = 2048;
constexpr int D = 512;
constexpr int D4 = D / 4;                      // 128 float4 per row
constexpr int CHUNK = 16;                      // timesteps per warp
constexpr int CHUNKS_PER_SEQ = S / CHUNK;      // 128
constexpr int THREADS = 256;                   // 8 warps/block  (R1 config — measured best)
constexpr int WARPS_PER_BLOCK = THREADS / 32;
constexpr int TOTAL_WARPS = B * CHUNKS_PER_SEQ;       // 8192
constexpr int GRID1 = TOTAL_WARPS / WARPS_PER_BLOCK;  // 1024 blocks

// Per-batch running max (float bits as int; all d >= 0 so int-compare == float-compare).
// Zero-initialized at module load; graph replays recompute the same max (idempotent).
__device__ int g_batchmax[B];

// Kernel 1: unnormalized squared L2 of consecutive-row diffs + per-batch atomic max.
// Each warp handles timesteps [s0, s0+CHUNK) of one batch, streaming rows so each
// input row is read ~once (prev row held in 4 float4 regs/lane).
__global__ void __launch_bounds__(THREADS)
l2_diff_kernel(const float4* __restrict__ x, float* __restrict__ out) {
    const int warp = (blockIdx.x * THREADS + threadIdx.x) >> 5;
    const int lane = threadIdx.x & 31;
    const int b    = warp / CHUNKS_PER_SEQ;
    const int s0   = (warp % CHUNKS_PER_SEQ) * CHUNK;

    const float4* base = x + (size_t)b * S * D4;

    // previous row: s0-1, except the very first chunk where d[0] = 0
    const int sprev = (s0 == 0) ? 0 : (s0 - 1);
    const float4* rowp = base + (size_t)sprev * D4;
    float4 prev[4];
    #pragma unroll
    for (int j = 0; j < 4; ++j) prev[j] = rowp[lane + 32 * j];

    if (s0 == 0 && lane == 0) out[(size_t)b * S] = 0.0f;

    const int s_start = (s0 == 0) ? 1 : s0;
    const int s_end   = s0 + CHUNK;

    float wmax = 0.0f;  // d >= 0, so 0 is a valid identity (and d[0] = 0)

    for (int s = s_start; s < s_end; ++s) {
        const float4* row = base + (size_t)s * D4;
        float sum = 0.0f;
        #pragma unroll
        for (int j = 0; j < 4; ++j) {
            float4 c = row[lane + 32 * j];
            float dx = c.x - prev[j].x;
            float dy = c.y - prev[j].y;
            float dz = c.z - prev[j].z;
            float dw = c.w - prev[j].w;
            sum += dx * dx + dy * dy + dz * dz + dw * dw;
            prev[j] = c;
        }
        // warp reduce (sum over D); all lanes end with the full sum
        #pragma unroll
        for (int off = 16; off > 0; off >>= 1)
            sum += __shfl_xor_sync(0xffffffffu, sum, off);
        wmax = fmaxf(wmax, sum);
        if (lane == 0) out[(size_t)b * S + s] = sum;
    }

    if (lane == 0) atomicMax(&g_batchmax[b], __float_as_int(wmax));
}

// Kernel 2: pure elementwise scale. One float2 of `out` per thread, 65536 threads
// total (4x the parallelism of the float4 variant) to hide DRAM/L2 latency.
constexpr int NTHREADS2 = 256;
constexpr int F2_PER_SEQ = S / 2;                       // 1024 float2 per batch
constexpr int GRID2 = (B * S / 2) / NTHREADS2;          // 256 blocks

__global__ void __launch_bounds__(NTHREADS2)
normalize_kernel(float2* __restrict__ out) {
    const int i = blockIdx.x * NTHREADS2 + threadIdx.x;  // float2 index
    const int b = i / F2_PER_SEQ;
    const float inv = 1.0f / __int_as_float(g_batchmax[b]);
    float2 v = out[i];
    v.x *= inv; v.y *= inv;
    out[i] = v;
}

extern "C" void kernel_launch(void* const* d_in, const int* in_sizes, int n_in,
                              void* d_out, int out_size) {
    const float4* x = (const float4*)d_in[0];
    (void)in_sizes; (void)n_in; (void)out_size;

    l2_diff_kernel<<<GRID1, THREADS>>>(x, (float*)d_out);
    normalize_kernel<<<GRID2, NTHREADS2>>>((float2*)d_out);
}

// round 5
// speedup vs baseline: 1.1642x; 1.1642x over previous
#include <cuda_runtime.h>

// Problem shape (fixed by reference setup_inputs): [B=64, S=2048, D=512] fp32
constexpr int B = 64;
constexpr int S = 2048;
constexpr int D = 512;
constexpr int D4 = D / 4;                      // 128 float4 per row
constexpr int CHUNK = 16;                      // timesteps per warp
constexpr int CHUNKS_PER_SEQ = S / CHUNK;      // 128
constexpr int THREADS = 256;                   // 8 warps/block (R1 config — measured best)
constexpr int WARPS_PER_BLOCK = THREADS / 32;
constexpr int TOTAL_WARPS = B * CHUNKS_PER_SEQ;       // 8192
constexpr int GRID1 = TOTAL_WARPS / WARPS_PER_BLOCK;  // 1024 blocks

// Kernel 1: unnormalized squared L2 of consecutive-row diffs. EXACT R1 version —
// no atomics, no extra globals (R3/R4 showed an atomicMax tail costs ~9us here).
__global__ void __launch_bounds__(THREADS)
l2_diff_kernel(const float4* __restrict__ x, float* __restrict__ out) {
    const int warp = (blockIdx.x * THREADS + threadIdx.x) >> 5;
    const int lane = threadIdx.x & 31;
    const int b    = warp / CHUNKS_PER_SEQ;
    const int s0   = (warp % CHUNKS_PER_SEQ) * CHUNK;

    const float4* base = x + (size_t)b * S * D4;

    // previous row: s0-1, except the very first chunk where d[0] = 0
    const int sprev = (s0 == 0) ? 0 : (s0 - 1);
    const float4* rowp = base + (size_t)sprev * D4;
    float4 prev[4];
    #pragma unroll
    for (int j = 0; j < 4; ++j) prev[j] = rowp[lane + 32 * j];

    if (s0 == 0 && lane == 0) out[(size_t)b * S] = 0.0f;

    const int s_start = (s0 == 0) ? 1 : s0;
    const int s_end   = s0 + CHUNK;

    for (int s = s_start; s < s_end; ++s) {
        const float4* row = base + (size_t)s * D4;
        float sum = 0.0f;
        #pragma unroll
        for (int j = 0; j < 4; ++j) {
            float4 c = row[lane + 32 * j];
            float dx = c.x - prev[j].x;
            float dy = c.y - prev[j].y;
            float dz = c.z - prev[j].z;
            float dw = c.w - prev[j].w;
            sum += dx * dx + dy * dy + dz * dz + dw * dw;
            prev[j] = c;
        }
        // warp reduce (sum over D)
        #pragma unroll
        for (int off = 16; off > 0; off >>= 1)
            sum += __shfl_xor_sync(0xffffffffu, sum, off);
        if (lane == 0) out[(size_t)b * S + s] = sum;
    }
}

// Kernel 2: fused max+scale, one block per batch, single pass.
// 512 threads; each thread owns exactly one float4 of the 2048-float row.
// Load once into registers -> shuffle max -> one smem stage -> scale regs -> store.
constexpr int NTHREADS2 = 512;                 // = S/4 float4 per row
constexpr int NWARPS2 = NTHREADS2 / 32;        // 16

__global__ void __launch_bounds__(NTHREADS2)
normalize_kernel(float4* __restrict__ out) {
    const int b = blockIdx.x;
    float4* row = out + (size_t)b * (S / 4);

    float4 v = row[threadIdx.x];
    float m = fmaxf(fmaxf(v.x, v.y), fmaxf(v.z, v.w));

    // warp max
    #pragma unroll
    for (int off = 16; off > 0; off >>= 1)
        m = fmaxf(m, __shfl_xor_sync(0xffffffffu, m, off));

    __shared__ float s_wmax[NWARPS2];
    __shared__ float s_inv;
    const int wid = threadIdx.x >> 5;
    const int lid = threadIdx.x & 31;
    if (lid == 0) s_wmax[wid] = m;
    __syncthreads();

    if (threadIdx.x < 32) {
        float t = (threadIdx.x < NWARPS2) ? s_wmax[threadIdx.x] : 0.0f;
        #pragma unroll
        for (int off = 8; off > 0; off >>= 1)
            t = fmaxf(t, __shfl_xor_sync(0xffffffffu, t, off));
        if (threadIdx.x == 0) s_inv = 1.0f / t;
    }
    __syncthreads();

    const float inv = s_inv;
    v.x *= inv; v.y *= inv; v.z *= inv; v.w *= inv;
    row[threadIdx.x] = v;
}

extern "C" void kernel_launch(void* const* d_in, const int* in_sizes, int n_in,
                              void* d_out, int out_size) {
    const float4* x = (const float4*)d_in[0];
    (void)in_sizes; (void)n_in; (void)out_size;

    l2_diff_kernel<<<GRID1, THREADS>>>(x, (float*)d_out);
    normalize_kernel<<<B, NTHREADS2>>>((float4*)d_out);
}